// round 1
// baseline (speedup 1.0000x reference)
#include <cuda_runtime.h>
#include <cuda_bf16.h>
#include <stdint.h>

// Problem dims (fixed by the dataset)
constexpr int M_ = 4096;    // batch B
constexpr int K_ = 2048;    // D (encode inner dim)
constexpr int N_ = 16384;   // L (latent)
constexpr int TOPK = 64;

// Compact top-k lists (scratch; device globals per harness rules)
__device__ float g_topv[M_ * TOPK];
__device__ int   g_topi[M_ * TOPK];

// ---------------------------------------------------------------------------
// Kernel 1: z = x @ W_enc + b_enc   (M=4096, K=2048, N=16384), fp32 SIMT GEMM
// Classic 128x128x8 tile, 256 threads, 8x8 per thread, float4 global loads.
// ---------------------------------------------------------------------------
__global__ void __launch_bounds__(256) enc_gemm_kernel(
    const float* __restrict__ A,   // x [M,K]
    const float* __restrict__ B,   // W_enc [K,N]
    const float* __restrict__ bias,// b_enc [N]
    float* __restrict__ C)         // z [M,N]
{
    constexpr int BM = 128, BN = 128, BK = 8, TM = 8, TN = 8;
    __shared__ float As[BK][BM];
    __shared__ float Bs[BK][BN];

    const int tid = threadIdx.x;
    const int tx = tid & 15;        // 0..15 column group
    const int ty = tid >> 4;        // 0..15 row group
    const int row0 = blockIdx.y * BM;
    const int col0 = blockIdx.x * BN;

    // A tile load map: 128 rows x 8 k, one float4 per thread
    const int ar = tid >> 1;
    const int ak = (tid & 1) * 4;
    // B tile load map: 8 rows x 128 cols, one float4 per thread
    const int br = tid >> 5;
    const int bc = (tid & 31) * 4;

    float acc[TM][TN] = {};

    const float* Aptr = A + (size_t)row0 * K_;
    const float* Bptr = B + col0;

    for (int kt = 0; kt < K_; kt += BK) {
        float4 a4 = *(const float4*)(Aptr + (size_t)ar * K_ + kt + ak);
        As[ak + 0][ar] = a4.x;
        As[ak + 1][ar] = a4.y;
        As[ak + 2][ar] = a4.z;
        As[ak + 3][ar] = a4.w;
        float4 b4 = *(const float4*)(Bptr + (size_t)(kt + br) * N_ + bc);
        *(float4*)&Bs[br][bc] = b4;
        __syncthreads();

        #pragma unroll
        for (int kk = 0; kk < BK; kk++) {
            float ra[TM], rb[TN];
            #pragma unroll
            for (int i = 0; i < TM; i++) ra[i] = As[kk][ty * TM + i];
            #pragma unroll
            for (int j = 0; j < TN; j++) rb[j] = Bs[kk][tx * TN + j];
            #pragma unroll
            for (int i = 0; i < TM; i++)
                #pragma unroll
                for (int j = 0; j < TN; j++)
                    acc[i][j] += ra[i] * rb[j];
        }
        __syncthreads();
    }

    // Epilogue: add bias, store
    #pragma unroll
    for (int i = 0; i < TM; i++) {
        const int r = row0 + ty * TM + i;
        #pragma unroll
        for (int j = 0; j < TN; j += 4) {
            const int c = col0 + tx * TN + j;
            float4 o;
            o.x = acc[i][j + 0] + bias[c + 0];
            o.y = acc[i][j + 1] + bias[c + 1];
            o.z = acc[i][j + 2] + bias[c + 2];
            o.w = acc[i][j + 3] + bias[c + 3];
            *(float4*)(C + (size_t)r * N_ + c) = o;
        }
    }
}

// ---------------------------------------------------------------------------
// Kernel 2: per-row exact top-64 by |z| (radix select over fp32 bits of |z|),
// tie-break by ascending index (matches stable lax.top_k). Sparsifies z
// in place and emits compact (val, idx) lists with DETERMINISTIC ordering.
// One block (256 threads) per row; row cached in 64KB dynamic smem.
// ---------------------------------------------------------------------------
__global__ void __launch_bounds__(256) topk_kernel(float* __restrict__ z)
{
    extern __shared__ float srow[];          // 16384 floats
    __shared__ unsigned int hist[256];
    __shared__ unsigned int s_prefix;
    __shared__ int s_r;
    __shared__ int s_counts[256];
    __shared__ int s_eqidx[256];
    __shared__ int s_eqcnt;
    __shared__ int s_idxcut;

    const int row = blockIdx.x;
    const int tid = threadIdx.x;
    float* zrow = z + (size_t)row * N_;

    // Load row into smem (coalesced float4)
    for (int i = tid; i < N_ / 4; i += 256)
        ((float4*)srow)[i] = ((const float4*)zrow)[i];
    if (tid == 0) { s_prefix = 0u; s_r = TOPK; s_eqcnt = 0; }
    __syncthreads();

    // 4-pass radix select (8 bits/pass) on key = bits(|z|)  (uint order == float order for >=0)
    for (int shift = 24; shift >= 0; shift -= 8) {
        hist[tid] = 0;
        __syncthreads();
        const unsigned int pfx = s_prefix;
        const unsigned int mask_hi = (shift == 24) ? 0u : (0xFFFFFFFFu << (shift + 8));
        for (int i = tid; i < N_; i += 256) {
            unsigned int key = __float_as_uint(fabsf(srow[i]));
            if ((key & mask_hi) == pfx)
                atomicAdd(&hist[(key >> shift) & 255u], 1u);
        }
        __syncthreads();
        if (tid == 0) {
            int r = s_r;
            int b = 255;
            for (; b > 0; b--) {
                int c = (int)hist[b];
                if (c >= r) break;
                r -= c;
            }
            s_r = r;
            s_prefix = pfx | ((unsigned int)b << shift);
        }
        __syncthreads();
    }
    const unsigned int T = s_prefix;   // threshold key
    const int need_eq = s_r;           // how many key==T to keep (smallest indices first)

    // Collect indices of elements equal to threshold
    for (int i = tid; i < N_; i += 256) {
        unsigned int key = __float_as_uint(fabsf(srow[i]));
        if (key == T) {
            int p = atomicAdd(&s_eqcnt, 1);
            if (p < 256) s_eqidx[p] = i;
        }
    }
    __syncthreads();
    if (tid == 0) {
        const int E = min(s_eqcnt, 256);
        int cut = 0x7FFFFFFF;
        if (E > need_eq) {
            // find need_eq-th smallest index among equals (E is tiny in practice)
            int last = -1;
            for (int t = 0; t < need_eq; t++) {
                int mn = 0x7FFFFFFF;
                for (int e = 0; e < E; e++) {
                    int v = s_eqidx[e];
                    if (v > last && v < mn) mn = v;
                }
                last = mn;
            }
            cut = last;
        }
        s_idxcut = cut;
    }
    __syncthreads();
    const int idxcut = s_idxcut;

    // Deterministic compaction: per-thread count + block scan
    int mycount = 0;
    for (int i = tid; i < N_; i += 256) {
        unsigned int key = __float_as_uint(fabsf(srow[i]));
        mycount += ((key > T) || (key == T && i <= idxcut)) ? 1 : 0;
    }
    s_counts[tid] = mycount;
    __syncthreads();
    for (int off = 1; off < 256; off <<= 1) {
        int v = s_counts[tid];
        int add = (tid >= off) ? s_counts[tid - off] : 0;
        __syncthreads();
        s_counts[tid] = v + add;
        __syncthreads();
    }
    int pos = s_counts[tid] - mycount;   // exclusive prefix

    // Write sparsified row + compact lists
    for (int i = tid; i < N_; i += 256) {
        float v = srow[i];
        unsigned int key = __float_as_uint(fabsf(v));
        bool sel = (key > T) || (key == T && i <= idxcut);
        zrow[i] = sel ? v : 0.0f;
        if (sel) {
            g_topv[row * TOPK + pos] = v;
            g_topi[row * TOPK + pos] = i;
            pos++;
        }
    }
}

// ---------------------------------------------------------------------------
// Kernel 3: recon[row,:] = b_dec + sum_j topv[j] * W_dec[topi[j], :]
// One block (256 threads) per row, 8 output cols per thread (2x float4).
// ---------------------------------------------------------------------------
__global__ void __launch_bounds__(256) dec_kernel(
    const float* __restrict__ Wd,   // [N_, K_] = [16384, 2048]
    const float* __restrict__ bd,   // [2048]
    float* __restrict__ recon)      // [M_, 2048]
{
    __shared__ float sv[TOPK];
    __shared__ int   si[TOPK];
    const int row = blockIdx.x;
    const int tid = threadIdx.x;
    if (tid < TOPK) {
        sv[tid] = g_topv[row * TOPK + tid];
        si[tid] = g_topi[row * TOPK + tid];
    }
    __syncthreads();

    const int c0 = tid * 4;          // 0..1023
    const int c1 = 1024 + tid * 4;   // 1024..2047
    float4 a0 = *(const float4*)(bd + c0);
    float4 a1 = *(const float4*)(bd + c1);

    #pragma unroll 4
    for (int j = 0; j < TOPK; j++) {
        const float v = sv[j];
        const float* wr = Wd + (size_t)si[j] * 2048;
        float4 w0 = *(const float4*)(wr + c0);
        float4 w1 = *(const float4*)(wr + c1);
        a0.x += v * w0.x; a0.y += v * w0.y; a0.z += v * w0.z; a0.w += v * w0.w;
        a1.x += v * w1.x; a1.y += v * w1.y; a1.z += v * w1.z; a1.w += v * w1.w;
    }

    float* out = recon + (size_t)row * 2048;
    *(float4*)(out + c0) = a0;
    *(float4*)(out + c1) = a1;
}

// ---------------------------------------------------------------------------
// Launch: z is materialized directly into d_out's z_sparse region (scratch),
// then sparsified in place. Output layout: [recon (4096x2048), z_sparse (4096x16384)].
// ---------------------------------------------------------------------------
extern "C" void kernel_launch(void* const* d_in, const int* in_sizes, int n_in,
                              void* d_out, int out_size)
{
    const float* x     = (const float*)d_in[0];
    const float* W_enc = (const float*)d_in[1];
    const float* b_enc = (const float*)d_in[2];
    const float* W_dec = (const float*)d_in[3];
    const float* b_dec = (const float*)d_in[4];

    float* recon = (float*)d_out;
    float* zsp   = (float*)d_out + (size_t)M_ * 2048;

    // Enable 64KB dynamic smem for topk (idempotent, capture-safe)
    cudaFuncSetAttribute(topk_kernel, cudaFuncAttributeMaxDynamicSharedMemorySize, 66560);

    dim3 gemm_grid(N_ / 128, M_ / 128);
    enc_gemm_kernel<<<gemm_grid, 256>>>(x, W_enc, b_enc, zsp);
    topk_kernel<<<M_, 256, N_ * (int)sizeof(float)>>>(zsp);
    dec_kernel<<<M_, 256>>>(W_dec, b_dec, recon);
}

// round 3
// speedup vs baseline: 2.6288x; 2.6288x over previous
#include <cuda_runtime.h>
#include <cuda_bf16.h>
#include <stdint.h>

constexpr int M_ = 4096;     // batch B
constexpr int K_ = 2048;     // D
constexpr int N_ = 16384;    // L
constexpr int TOPK = 64;
constexpr float MARGIN = 2e-4f;   // selection ambiguity band (~28 sigma of split-bf16 error)

// ---------------- scratch (device globals; no allocs allowed) ----------------
__device__ __align__(256) __nv_bfloat16 g_xhi[M_ * K_];
__device__ __align__(256) __nv_bfloat16 g_xlo[M_ * K_];
__device__ __align__(256) __nv_bfloat16 g_whiT[(size_t)N_ * K_];  // W_enc^T hi, [N,K]
__device__ __align__(256) __nv_bfloat16 g_wloT[(size_t)N_ * K_];  // W_enc^T lo
__device__ float g_topv[M_ * TOPK];
__device__ int   g_topi[M_ * TOPK];
__device__ int   g_flag[M_];
__device__ int   g_slots[M_];
__device__ int   g_bandcnt[M_];
__device__ int   g_bandidx[M_ * 64];

// ---------------- helpers (family-safe ISA only: sm_80/90 base) ----------------
__device__ __forceinline__ uint32_t smem_u32(const void* p) {
    uint32_t a;
    asm("{ .reg .u64 t; cvta.to.shared.u64 t, %1; cvt.u32.u64 %0, t; }" : "=r"(a) : "l"(p));
    return a;
}
__device__ __forceinline__ void cp_async16(uint32_t s, const void* g) {
    asm volatile("cp.async.cg.shared.global [%0], [%1], 16;" :: "r"(s), "l"(g));
}
__device__ __forceinline__ void ldmatrix4(uint32_t* r, uint32_t addr) {
    asm volatile("ldmatrix.sync.aligned.m8n8.x4.shared.b16 {%0,%1,%2,%3}, [%4];"
                 : "=r"(r[0]), "=r"(r[1]), "=r"(r[2]), "=r"(r[3]) : "r"(addr));
}
__device__ __forceinline__ void mma16816(float* d, const uint32_t* a, uint32_t b0, uint32_t b1) {
    asm volatile(
        "mma.sync.aligned.m16n8k16.row.col.f32.bf16.bf16.f32 "
        "{%0,%1,%2,%3}, {%4,%5,%6,%7}, {%8,%9}, {%0,%1,%2,%3};"
        : "+f"(d[0]), "+f"(d[1]), "+f"(d[2]), "+f"(d[3])
        : "r"(a[0]), "r"(a[1]), "r"(a[2]), "r"(a[3]), "r"(b0), "r"(b1));
}

// ---------------- conversion kernels ----------------
__global__ void __launch_bounds__(256) conv_x_kernel(const float* __restrict__ x) {
    int i = blockIdx.x * 256 + threadIdx.x;
    if (i < M_ * K_) {
        float v = x[i];
        __nv_bfloat16 h = __float2bfloat16(v);
        g_xhi[i] = h;
        g_xlo[i] = __float2bfloat16(v - __bfloat162float(h));
    }
}

// W_enc [K,N] -> transposed hi/lo bf16 [N,K]
__global__ void __launch_bounds__(256) conv_w_kernel(const float* __restrict__ W) {
    __shared__ float t[32][33];
    const int tx = threadIdx.x, ty = threadIdx.y;   // 32 x 8
    const int n0 = blockIdx.x * 32, k0 = blockIdx.y * 32;
    #pragma unroll
    for (int j = 0; j < 4; j++)
        t[ty + j * 8][tx] = W[(size_t)(k0 + ty + j * 8) * N_ + (n0 + tx)];
    __syncthreads();
    #pragma unroll
    for (int j = 0; j < 4; j++) {
        float v = t[tx][ty + j * 8];
        __nv_bfloat16 h = __float2bfloat16(v);
        size_t o = (size_t)(n0 + ty + j * 8) * K_ + (k0 + tx);
        g_whiT[o] = h;
        g_wloT[o] = __float2bfloat16(v - __bfloat162float(h));
    }
}

// ---------------- split-bf16 encode GEMM via mma.sync (HMMA) ----------------
// z[128x128 tile] = sum of 3 segments {(xhi,whi),(xlo,whi),(xhi,wlo)}, K=2048 each.
// 8 warps, warp tile 32x64, BK=64, 2-stage cp.async pipeline, padded smem rows.
constexpr int ROWB = 144;               // 64 bf16 = 128B, +16B pad (conflict-free ldmatrix)
constexpr int TILEB = 128 * ROWB;       // 18432 B per operand tile
constexpr int STAGEB = 2 * TILEB;       // A+B per stage
constexpr int GEMM_SMEM = 2 * STAGEB;   // 73728 B

__global__ void __launch_bounds__(256, 2) enc_gemm_mma(const float* __restrict__ b_enc,
                                                       float* __restrict__ C) {
    extern __shared__ char sm[];
    const uint32_t base = smem_u32(sm);
    const int tid = threadIdx.x, lane = tid & 31, wid = tid >> 5;
    const int wm = wid & 3, wn = wid >> 2;          // 4x2 warp grid
    const int row0 = blockIdx.x * 128;              // M tile (fastest -> B reuse in L2)
    const int col0 = blockIdx.y * 128;              // N tile

    const __nv_bfloat16* segA[3] = { g_xhi, g_xlo, g_xhi };
    const __nv_bfloat16* segB[3] = { g_whiT, g_whiT, g_wloT };

    float c[2][8][4];
    #pragma unroll
    for (int i = 0; i < 2; i++)
        #pragma unroll
        for (int j = 0; j < 8; j++)
            #pragma unroll
            for (int q = 0; q < 4; q++) c[i][j][q] = 0.f;

    auto issue = [&](int ch) {
        const int sg = ch >> 5;
        const int kk = (ch & 31) * 64;
        const uint32_t st = base + (ch & 1) * STAGEB;
        const __nv_bfloat16* A = segA[sg];
        const __nv_bfloat16* B = segB[sg];
        #pragma unroll
        for (int j = 0; j < 4; j++) {
            const int slot = tid + 256 * j;         // 0..1023
            const int r = slot >> 3, cc = slot & 7; // 128 rows x 8 x 16B
            cp_async16(st + r * ROWB + cc * 16,
                       A + (size_t)(row0 + r) * K_ + kk + cc * 8);
            cp_async16(st + TILEB + r * ROWB + cc * 16,
                       B + (size_t)(col0 + r) * K_ + kk + cc * 8);
        }
        asm volatile("cp.async.commit_group;");
    };

    auto compute = [&](int s) {
        const uint32_t sa = base + s * STAGEB;
        const uint32_t sb = sa + TILEB;
        #pragma unroll
        for (int ks = 0; ks < 4; ks++) {
            uint32_t a[2][4];
            #pragma unroll
            for (int mi = 0; mi < 2; mi++) {
                const int row = wm * 32 + mi * 16 + (lane & 15);
                ldmatrix4(a[mi], sa + row * ROWB + ks * 32 + ((lane >> 4) << 4));
            }
            uint32_t b[4][4];
            #pragma unroll
            for (int nl = 0; nl < 4; nl++) {
                const int row = wn * 64 + nl * 16 + (lane & 7) + ((lane >> 4) << 3);
                ldmatrix4(b[nl], sb + row * ROWB + ks * 32 + (((lane >> 3) & 1) << 4));
            }
            #pragma unroll
            for (int mi = 0; mi < 2; mi++)
                #pragma unroll
                for (int nl = 0; nl < 4; nl++) {
                    mma16816(c[mi][2 * nl + 0], a[mi], b[nl][0], b[nl][1]);
                    mma16816(c[mi][2 * nl + 1], a[mi], b[nl][2], b[nl][3]);
                }
        }
    };

    issue(0);
    for (int i = 0; i < 96; i++) {
        if (i + 1 < 96) {
            issue(i + 1);
            asm volatile("cp.async.wait_group 1;");
        } else {
            asm volatile("cp.async.wait_group 0;");
        }
        __syncthreads();
        compute(i & 1);
        __syncthreads();
    }

    // epilogue: add bias, store fp32 z
    const int gid = lane >> 2, tig = lane & 3;
    #pragma unroll
    for (int mi = 0; mi < 2; mi++) {
        const int r0 = row0 + wm * 32 + mi * 16 + gid;
        #pragma unroll
        for (int ni = 0; ni < 8; ni++) {
            const int cc = col0 + wn * 64 + ni * 8 + 2 * tig;
            const float2 bb = *(const float2*)(b_enc + cc);
            float2 v0 = { c[mi][ni][0] + bb.x, c[mi][ni][1] + bb.y };
            float2 v1 = { c[mi][ni][2] + bb.x, c[mi][ni][3] + bb.y };
            *(float2*)(C + (size_t)r0 * N_ + cc) = v0;
            *(float2*)(C + (size_t)(r0 + 8) * N_ + cc) = v1;
        }
    }
}

// ---------------- top-k with ambiguity-band detection ----------------
__global__ void __launch_bounds__(256) topk_kernel(float* __restrict__ z) {
    extern __shared__ float srow[];          // 16384 floats
    __shared__ unsigned int hist[256];
    __shared__ unsigned int s_prefix;
    __shared__ int s_r;
    __shared__ int s_counts[256];
    __shared__ int s_eqidx[256];
    __shared__ int s_eqcnt;
    __shared__ int s_idxcut;
    __shared__ int s_above, s_nb;

    const int row = blockIdx.x;
    const int tid = threadIdx.x;
    float* zrow = z + (size_t)row * N_;

    for (int i = tid; i < N_ / 4; i += 256)
        ((float4*)srow)[i] = ((const float4*)zrow)[i];
    if (tid == 0) { s_prefix = 0u; s_r = TOPK; s_eqcnt = 0; s_above = 0; s_nb = 0; }
    __syncthreads();

    for (int shift = 24; shift >= 0; shift -= 8) {
        hist[tid] = 0;
        __syncthreads();
        const unsigned int pfx = s_prefix;
        const unsigned int mask_hi = (shift == 24) ? 0u : (0xFFFFFFFFu << (shift + 8));
        for (int i = tid; i < N_; i += 256) {
            unsigned int key = __float_as_uint(fabsf(srow[i]));
            if ((key & mask_hi) == pfx)
                atomicAdd(&hist[(key >> shift) & 255u], 1u);
        }
        __syncthreads();
        if (tid == 0) {
            int r = s_r, b = 255;
            for (; b > 0; b--) { int cnt = (int)hist[b]; if (cnt >= r) break; r -= cnt; }
            s_r = r;
            s_prefix = pfx | ((unsigned int)b << shift);
        }
        __syncthreads();
    }
    const unsigned int T = s_prefix;
    const int need_eq = s_r;

    for (int i = tid; i < N_; i += 256) {
        unsigned int key = __float_as_uint(fabsf(srow[i]));
        if (key == T) { int p = atomicAdd(&s_eqcnt, 1); if (p < 256) s_eqidx[p] = i; }
    }
    __syncthreads();
    if (tid == 0) {
        const int E = min(s_eqcnt, 256);
        int cut = 0x7FFFFFFF;
        if (E > need_eq) {
            int last = -1;
            for (int t = 0; t < need_eq; t++) {
                int mn = 0x7FFFFFFF;
                for (int e = 0; e < E; e++) { int v = s_eqidx[e]; if (v > last && v < mn) mn = v; }
                last = mn;
            }
            cut = last;
        }
        s_idxcut = cut;
    }
    __syncthreads();
    const int idxcut = s_idxcut;

    // ambiguity band around the approx threshold
    const float tval = __uint_as_float(T);
    const float blo = tval - MARGIN, bhi = tval + MARGIN;
    int myab = 0;
    for (int i = tid; i < N_; i += 256) {
        float av = fabsf(srow[i]);
        if (av > bhi) myab++;
        else if (av >= blo) { int p = atomicAdd(&s_nb, 1); if (p < 64) g_bandidx[row * 64 + p] = i; }
    }
    atomicAdd(&s_above, myab);
    __syncthreads();
    if (tid == 0) {
        int nbr = s_nb, slots = TOPK - s_above;
        g_bandcnt[row] = min(nbr, 64);
        g_slots[row] = slots;
        g_flag[row] = (nbr > slots) ? 1 : 0;
    }

    // deterministic compaction of approx top-64
    int mycount = 0;
    for (int i = tid; i < N_; i += 256) {
        unsigned int key = __float_as_uint(fabsf(srow[i]));
        mycount += ((key > T) || (key == T && i <= idxcut)) ? 1 : 0;
    }
    s_counts[tid] = mycount;
    __syncthreads();
    for (int off = 1; off < 256; off <<= 1) {
        int v = s_counts[tid];
        int add = (tid >= off) ? s_counts[tid - off] : 0;
        __syncthreads();
        s_counts[tid] = v + add;
        __syncthreads();
    }
    int pos = s_counts[tid] - mycount;
    for (int i = tid; i < N_; i += 256) {
        float v = srow[i];
        unsigned int key = __float_as_uint(fabsf(v));
        bool sel = (key > T) || (key == T && i <= idxcut);
        zrow[i] = sel ? v : 0.0f;
        if (sel) {
            g_topv[row * TOPK + pos] = v;
            g_topi[row * TOPK + pos] = i;
            pos++;
        }
    }
}

// ---------------- exact refinement for flagged rows ----------------
__global__ void __launch_bounds__(256) refine_kernel(
    const float* __restrict__ x, const float* __restrict__ W_enc,
    const float* __restrict__ b_enc, float* __restrict__ z) {
    const int row = blockIdx.x;
    if (!g_flag[row]) return;
    __shared__ float sx[K_];
    __shared__ float s_exact[64];
    __shared__ int s_keep[64];
    __shared__ int s_cnt[256];
    const int tid = threadIdx.x, lid = tid & 31, wrp = tid >> 5;
    const int nb = g_bandcnt[row], slots = g_slots[row];

    for (int i = tid; i < K_; i += 256) sx[i] = x[(size_t)row * K_ + i];
    __syncthreads();

    for (int e = wrp; e < nb; e += 8) {
        const int j = g_bandidx[row * 64 + e];
        float acc = 0.f;
        for (int k = lid; k < K_; k += 32)
            acc = fmaf(sx[k], W_enc[(size_t)k * N_ + j], acc);
        #pragma unroll
        for (int o = 16; o; o >>= 1) acc += __shfl_xor_sync(0xFFFFFFFFu, acc, o);
        if (lid == 0) s_exact[e] = acc + b_enc[j];
    }
    __syncthreads();
    if (tid < nb) {
        const float mv = fabsf(s_exact[tid]);
        const int mi = g_bandidx[row * 64 + tid];
        int rank = 0;
        for (int f = 0; f < nb; f++) {
            if (f == tid) continue;
            const float fv = fabsf(s_exact[f]);
            const int fi = g_bandidx[row * 64 + f];
            if (fv > mv || (fv == mv && fi < mi)) rank++;
        }
        s_keep[tid] = (rank < slots) ? 1 : 0;
    }
    __syncthreads();
    float* zrow = z + (size_t)row * N_;
    if (tid < nb) {
        const int j = g_bandidx[row * 64 + tid];
        zrow[j] = s_keep[tid] ? s_exact[tid] : 0.0f;
    }
    __threadfence_block();
    __syncthreads();
    // rebuild compact list in index order
    int my = 0;
    for (int i = tid; i < N_; i += 256) my += (zrow[i] != 0.0f) ? 1 : 0;
    s_cnt[tid] = my;
    __syncthreads();
    for (int off = 1; off < 256; off <<= 1) {
        int v = s_cnt[tid];
        int a = (tid >= off) ? s_cnt[tid - off] : 0;
        __syncthreads();
        s_cnt[tid] = v + a;
        __syncthreads();
    }
    int pos = s_cnt[tid] - my;
    for (int i = tid; i < N_; i += 256) {
        float v = zrow[i];
        if (v != 0.0f) {
            if (pos < TOPK) { g_topv[row * TOPK + pos] = v; g_topi[row * TOPK + pos] = i; }
            pos++;
        }
    }
}

// ---------------- sparse decode ----------------
__global__ void __launch_bounds__(256) dec_kernel(
    const float* __restrict__ Wd, const float* __restrict__ bd,
    float* __restrict__ recon) {
    __shared__ float sv[TOPK];
    __shared__ int   si[TOPK];
    const int row = blockIdx.x;
    const int tid = threadIdx.x;
    if (tid < TOPK) { sv[tid] = g_topv[row * TOPK + tid]; si[tid] = g_topi[row * TOPK + tid]; }
    __syncthreads();

    const int c0 = tid * 4;
    const int c1 = 1024 + tid * 4;
    float4 a0 = *(const float4*)(bd + c0);
    float4 a1 = *(const float4*)(bd + c1);
    #pragma unroll 4
    for (int j = 0; j < TOPK; j++) {
        const float v = sv[j];
        const float* wr = Wd + (size_t)si[j] * 2048;
        float4 w0 = *(const float4*)(wr + c0);
        float4 w1 = *(const float4*)(wr + c1);
        a0.x += v * w0.x; a0.y += v * w0.y; a0.z += v * w0.z; a0.w += v * w0.w;
        a1.x += v * w1.x; a1.y += v * w1.y; a1.z += v * w1.z; a1.w += v * w1.w;
    }
    float* out = recon + (size_t)row * 2048;
    *(float4*)(out + c0) = a0;
    *(float4*)(out + c1) = a1;
}

// ---------------- launch ----------------
extern "C" void kernel_launch(void* const* d_in, const int* in_sizes, int n_in,
                              void* d_out, int out_size) {
    const float* x     = (const float*)d_in[0];
    const float* W_enc = (const float*)d_in[1];
    const float* b_enc = (const float*)d_in[2];
    const float* W_dec = (const float*)d_in[3];
    const float* b_dec = (const float*)d_in[4];

    float* recon = (float*)d_out;
    float* zsp   = (float*)d_out + (size_t)M_ * 2048;

    cudaFuncSetAttribute(topk_kernel, cudaFuncAttributeMaxDynamicSharedMemorySize, 66560);
    cudaFuncSetAttribute(enc_gemm_mma, cudaFuncAttributeMaxDynamicSharedMemorySize, GEMM_SMEM);

    conv_x_kernel<<<(M_ * K_ + 255) / 256, 256>>>(x);
    conv_w_kernel<<<dim3(N_ / 32, K_ / 32), dim3(32, 8)>>>(W_enc);
    enc_gemm_mma<<<dim3(M_ / 128, N_ / 128), 256, GEMM_SMEM>>>(b_enc, zsp);
    topk_kernel<<<M_, 256, N_ * (int)sizeof(float)>>>(zsp);
    refine_kernel<<<M_, 256>>>(x, W_enc, b_enc, zsp);
    dec_kernel<<<M_, 256>>>(W_dec, b_dec, recon);
}

// round 4
// speedup vs baseline: 4.4950x; 1.7099x over previous
#include <cuda_runtime.h>
#include <cuda_bf16.h>
#include <stdint.h>

constexpr int M_ = 4096;     // batch B
constexpr int K_ = 2048;     // D
constexpr int N_ = 16384;    // L
constexpr int TOPK = 64;
constexpr float MARGIN = 2e-2f;   // 12.5 sigma of hi-only bf16 GEMM error
constexpr int BANDCAP = 128;
constexpr int CANDCAP = 192;      // 64 provisional + up to 128 band extras

// ---------------- scratch (device globals; no allocs allowed) ----------------
__device__ __align__(256) __nv_bfloat16 g_xhi[M_ * K_];
__device__ __align__(256) __nv_bfloat16 g_whiT[(size_t)N_ * K_];  // W_enc^T bf16-hi [N,K]
__device__ __align__(256) float g_wT[(size_t)N_ * K_];            // W_enc^T fp32 [N,K]
__device__ float g_topv[M_ * TOPK];
__device__ int   g_topi[M_ * TOPK];
__device__ int   g_slots[M_];
__device__ int   g_bandcnt[M_];
__device__ float g_blo[M_];
__device__ int   g_bandidx[M_ * BANDCAP];   // idx | (sel << 31)

// ---------------- helpers (family-safe ISA: sm_80/90 base) ----------------
__device__ __forceinline__ uint32_t smem_u32(const void* p) {
    uint32_t a;
    asm("{ .reg .u64 t; cvta.to.shared.u64 t, %1; cvt.u32.u64 %0, t; }" : "=r"(a) : "l"(p));
    return a;
}
__device__ __forceinline__ void cp_async16(uint32_t s, const void* g) {
    asm volatile("cp.async.cg.shared.global [%0], [%1], 16;" :: "r"(s), "l"(g));
}
__device__ __forceinline__ void ldmatrix4(uint32_t* r, uint32_t addr) {
    asm volatile("ldmatrix.sync.aligned.m8n8.x4.shared.b16 {%0,%1,%2,%3}, [%4];"
                 : "=r"(r[0]), "=r"(r[1]), "=r"(r[2]), "=r"(r[3]) : "r"(addr));
}
__device__ __forceinline__ void mma16816(float* d, const uint32_t* a, uint32_t b0, uint32_t b1) {
    asm volatile(
        "mma.sync.aligned.m16n8k16.row.col.f32.bf16.bf16.f32 "
        "{%0,%1,%2,%3}, {%4,%5,%6,%7}, {%8,%9}, {%0,%1,%2,%3};"
        : "+f"(d[0]), "+f"(d[1]), "+f"(d[2]), "+f"(d[3])
        : "r"(a[0]), "r"(a[1]), "r"(a[2]), "r"(a[3]), "r"(b0), "r"(b1));
}

// ---------------- conversion kernels ----------------
__global__ void __launch_bounds__(256) conv_x_kernel(const float* __restrict__ x) {
    int i = blockIdx.x * 256 + threadIdx.x;
    if (i < M_ * K_) g_xhi[i] = __float2bfloat16(x[i]);
}

// W_enc [K,N] -> transposed [N,K]: bf16 hi + fp32 copy
__global__ void __launch_bounds__(256) conv_w_kernel(const float* __restrict__ W) {
    __shared__ float t[32][33];
    const int tx = threadIdx.x, ty = threadIdx.y;   // 32 x 8
    const int n0 = blockIdx.x * 32, k0 = blockIdx.y * 32;
    #pragma unroll
    for (int j = 0; j < 4; j++)
        t[ty + j * 8][tx] = W[(size_t)(k0 + ty + j * 8) * N_ + (n0 + tx)];
    __syncthreads();
    #pragma unroll
    for (int j = 0; j < 4; j++) {
        float v = t[tx][ty + j * 8];
        size_t o = (size_t)(n0 + ty + j * 8) * K_ + (k0 + tx);
        g_whiT[o] = __float2bfloat16(v);
        g_wT[o] = v;
    }
}

// ---------------- hi-only bf16 encode GEMM via mma.sync (HMMA) ----------------
// z ~= xhi @ whiT^T + b_enc   (K=2048), err sigma ~1.6e-3 (selection only; fixed later)
constexpr int ROWB = 144;               // 64 bf16 = 128B, +16B pad (conflict-free ldmatrix)
constexpr int TILEB = 128 * ROWB;
constexpr int STAGEB = 2 * TILEB;
constexpr int GEMM_SMEM = 2 * STAGEB;   // 73728 B

__global__ void __launch_bounds__(256, 2) enc_gemm_mma(const float* __restrict__ b_enc,
                                                       float* __restrict__ C) {
    extern __shared__ char sm[];
    const uint32_t base = smem_u32(sm);
    const int tid = threadIdx.x, lane = tid & 31, wid = tid >> 5;
    const int wm = wid & 3, wn = wid >> 2;          // 4x2 warp grid
    const int row0 = blockIdx.x * 128;              // M tile (fastest; xhi fully L2-resident)
    const int col0 = blockIdx.y * 128;              // N tile

    float c[2][8][4];
    #pragma unroll
    for (int i = 0; i < 2; i++)
        #pragma unroll
        for (int j = 0; j < 8; j++)
            #pragma unroll
            for (int q = 0; q < 4; q++) c[i][j][q] = 0.f;

    auto issue = [&](int ch) {
        const int kk = ch * 64;
        const uint32_t st = base + (ch & 1) * STAGEB;
        #pragma unroll
        for (int j = 0; j < 4; j++) {
            const int slot = tid + 256 * j;         // 0..1023
            const int r = slot >> 3, cc = slot & 7; // 128 rows x 8 x 16B
            cp_async16(st + r * ROWB + cc * 16,
                       g_xhi + (size_t)(row0 + r) * K_ + kk + cc * 8);
            cp_async16(st + TILEB + r * ROWB + cc * 16,
                       g_whiT + (size_t)(col0 + r) * K_ + kk + cc * 8);
        }
        asm volatile("cp.async.commit_group;");
    };

    auto compute = [&](int s) {
        const uint32_t sa = base + s * STAGEB;
        const uint32_t sb = sa + TILEB;
        #pragma unroll
        for (int ks = 0; ks < 4; ks++) {
            uint32_t a[2][4];
            #pragma unroll
            for (int mi = 0; mi < 2; mi++) {
                const int row = wm * 32 + mi * 16 + (lane & 15);
                ldmatrix4(a[mi], sa + row * ROWB + ks * 32 + ((lane >> 4) << 4));
            }
            uint32_t b[4][4];
            #pragma unroll
            for (int nl = 0; nl < 4; nl++) {
                const int row = wn * 64 + nl * 16 + (lane & 7) + ((lane >> 4) << 3);
                ldmatrix4(b[nl], sb + row * ROWB + ks * 32 + (((lane >> 3) & 1) << 4));
            }
            #pragma unroll
            for (int mi = 0; mi < 2; mi++)
                #pragma unroll
                for (int nl = 0; nl < 4; nl++) {
                    mma16816(c[mi][2 * nl + 0], a[mi], b[nl][0], b[nl][1]);
                    mma16816(c[mi][2 * nl + 1], a[mi], b[nl][2], b[nl][3]);
                }
        }
    };

    constexpr int NCH = 32;      // K=2048 / 64
    issue(0);
    for (int i = 0; i < NCH; i++) {
        if (i + 1 < NCH) {
            issue(i + 1);
            asm volatile("cp.async.wait_group 1;");
        } else {
            asm volatile("cp.async.wait_group 0;");
        }
        __syncthreads();
        compute(i & 1);
        __syncthreads();
    }

    const int gid = lane >> 2, tig = lane & 3;
    #pragma unroll
    for (int mi = 0; mi < 2; mi++) {
        const int r0 = row0 + wm * 32 + mi * 16 + gid;
        #pragma unroll
        for (int ni = 0; ni < 8; ni++) {
            const int cc = col0 + wn * 64 + ni * 8 + 2 * tig;
            const float2 bb = *(const float2*)(b_enc + cc);
            float2 v0 = { c[mi][ni][0] + bb.x, c[mi][ni][1] + bb.y };
            float2 v1 = { c[mi][ni][2] + bb.x, c[mi][ni][3] + bb.y };
            *(float2*)(C + (size_t)r0 * N_ + cc) = v0;
            *(float2*)(C + (size_t)(r0 + 8) * N_ + cc) = v1;
        }
    }
}

// ---------------- top-k (approx) with ambiguity band ----------------
__global__ void __launch_bounds__(256) topk_kernel(float* __restrict__ z) {
    extern __shared__ float srow[];          // 16384 floats
    __shared__ unsigned int hist[256];
    __shared__ unsigned int s_prefix;
    __shared__ int s_r;
    __shared__ int s_counts[256];
    __shared__ int s_eqidx[256];
    __shared__ int s_eqcnt;
    __shared__ int s_idxcut;
    __shared__ int s_above, s_nb;

    const int row = blockIdx.x;
    const int tid = threadIdx.x;
    float* zrow = z + (size_t)row * N_;

    for (int i = tid; i < N_ / 4; i += 256)
        ((float4*)srow)[i] = ((const float4*)zrow)[i];
    if (tid == 0) { s_prefix = 0u; s_r = TOPK; s_eqcnt = 0; s_above = 0; s_nb = 0; }
    __syncthreads();

    for (int shift = 24; shift >= 0; shift -= 8) {
        hist[tid] = 0;
        __syncthreads();
        const unsigned int pfx = s_prefix;
        const unsigned int mask_hi = (shift == 24) ? 0u : (0xFFFFFFFFu << (shift + 8));
        for (int i = tid; i < N_; i += 256) {
            unsigned int key = __float_as_uint(fabsf(srow[i]));
            if ((key & mask_hi) == pfx)
                atomicAdd(&hist[(key >> shift) & 255u], 1u);
        }
        __syncthreads();
        if (tid == 0) {
            int r = s_r, b = 255;
            for (; b > 0; b--) { int cnt = (int)hist[b]; if (cnt >= r) break; r -= cnt; }
            s_r = r;
            s_prefix = pfx | ((unsigned int)b << shift);
        }
        __syncthreads();
    }
    const unsigned int T = s_prefix;
    const int need_eq = s_r;

    for (int i = tid; i < N_; i += 256) {
        unsigned int key = __float_as_uint(fabsf(srow[i]));
        if (key == T) { int p = atomicAdd(&s_eqcnt, 1); if (p < 256) s_eqidx[p] = i; }
    }
    __syncthreads();
    if (tid == 0) {
        const int E = min(s_eqcnt, 256);
        int cut = 0x7FFFFFFF;
        if (E > need_eq) {
            int last = -1;
            for (int t = 0; t < need_eq; t++) {
                int mn = 0x7FFFFFFF;
                for (int e = 0; e < E; e++) { int v = s_eqidx[e]; if (v > last && v < mn) mn = v; }
                last = mn;
            }
            cut = last;
        }
        s_idxcut = cut;
    }
    __syncthreads();
    const int idxcut = s_idxcut;

    const float tval = __uint_as_float(T);
    const float blo = tval - MARGIN, bhi = tval + MARGIN;

    // count pass: selected count + above-band count
    int mycount = 0, myabove = 0;
    for (int i = tid; i < N_; i += 256) {
        float av = fabsf(srow[i]);
        unsigned int key = __float_as_uint(av);
        mycount += ((key > T) || (key == T && i <= idxcut)) ? 1 : 0;
        myabove += (av > bhi) ? 1 : 0;
    }
    atomicAdd(&s_above, myabove);
    s_counts[tid] = mycount;
    __syncthreads();
    for (int off = 1; off < 256; off <<= 1) {
        int v = s_counts[tid];
        int add = (tid >= off) ? s_counts[tid - off] : 0;
        __syncthreads();
        s_counts[tid] = v + add;
        __syncthreads();
    }
    int pos = s_counts[tid] - mycount;

    // write pass: dense sparsified row + compact lists + band list
    for (int i = tid; i < N_; i += 256) {
        float v = srow[i];
        float av = fabsf(v);
        unsigned int key = __float_as_uint(av);
        bool sel = (key > T) || (key == T && i <= idxcut);
        zrow[i] = sel ? v : 0.0f;
        if (sel) {
            g_topv[row * TOPK + pos] = v;
            g_topi[row * TOPK + pos] = i;
            pos++;
        }
        if (av >= blo && av <= bhi) {
            int p = atomicAdd(&s_nb, 1);
            if (p < BANDCAP)
                g_bandidx[row * BANDCAP + p] = i | (sel ? 0x80000000 : 0);
        }
    }
    __syncthreads();
    if (tid == 0) {
        g_bandcnt[row] = min(s_nb, BANDCAP);
        g_slots[row] = TOPK - s_above;
        g_blo[row] = blo;
    }
}

// ---------------- exact fixup: fp32 dots for candidates, exact re-rank ----------------
__global__ void __launch_bounds__(256) fixup_kernel(
    const float* __restrict__ x, const float* __restrict__ b_enc,
    float* __restrict__ z) {
    __shared__ float sx[K_];
    __shared__ int   s_idx[CANDCAP];
    __shared__ float s_val[CANDCAP];
    __shared__ unsigned char s_band[CANDCAP];
    __shared__ unsigned char s_keep[CANDCAP];
    __shared__ int s_nc;

    const int row = blockIdx.x;
    const int tid = threadIdx.x, lid = tid & 31, wrp = tid >> 5;
    const int nb = g_bandcnt[row], slots = g_slots[row];
    const float bhi = g_blo[row] + 2.0f * MARGIN;

    for (int i = tid; i < K_; i += 256) sx[i] = x[(size_t)row * K_ + i];
    if (tid == 0) s_nc = TOPK;

    // candidates 0..63: provisional selection (index-ascending)
    if (tid < TOPK) {
        float av = fabsf(g_topv[row * TOPK + tid]);
        s_idx[tid] = g_topi[row * TOPK + tid];
        s_band[tid] = (av <= bhi) ? 1 : 0;   // in-band provisional
        s_keep[tid] = 0;
    }
    __syncthreads();
    // candidates 64..: unselected band members
    if (tid < nb) {
        int e = g_bandidx[row * BANDCAP + tid];
        if (!(e & 0x80000000)) {
            int p = atomicAdd(&s_nc, 1);
            if (p < CANDCAP) {
                s_idx[p] = e;
                s_band[p] = 1;
                s_keep[p] = 0;
            }
        }
    }
    __syncthreads();
    const int nc = min(s_nc, CANDCAP);

    // exact fp32 dots (coalesced rows of g_wT)
    for (int c = wrp; c < nc; c += 8) {
        const int j = s_idx[c];
        const float* wr = g_wT + (size_t)j * K_;
        float a0 = 0.f, a1 = 0.f, a2 = 0.f, a3 = 0.f;
        for (int k = lid; k < K_; k += 128) {
            a0 = fmaf(sx[k],      wr[k],      a0);
            a1 = fmaf(sx[k + 32], wr[k + 32], a1);
            a2 = fmaf(sx[k + 64], wr[k + 64], a2);
            a3 = fmaf(sx[k + 96], wr[k + 96], a3);
        }
        float acc = (a0 + a1) + (a2 + a3);
        #pragma unroll
        for (int o = 16; o; o >>= 1) acc += __shfl_xor_sync(0xFFFFFFFFu, acc, o);
        if (lid == 0) s_val[c] = acc + b_enc[j];
    }
    __syncthreads();

    // keep: all above-band provisional + top-`slots` band candidates by (|exact|, idx)
    if (tid < nc) {
        if (!s_band[tid]) {
            s_keep[tid] = 1;
        } else {
            const float mv = fabsf(s_val[tid]);
            const int mi = s_idx[tid];
            int rank = 0;
            for (int f = 0; f < nc; f++) {
                if (!s_band[f] || f == tid) continue;
                const float fv = fabsf(s_val[f]);
                if (fv > mv || (fv == mv && s_idx[f] < mi)) rank++;
            }
            s_keep[tid] = (rank < slots) ? 1 : 0;
        }
    }
    __syncthreads();

    // write dense corrections + final compact lists (index-ascending)
    float* zrow = z + (size_t)row * N_;
    if (tid < nc) {
        zrow[s_idx[tid]] = s_keep[tid] ? s_val[tid] : 0.0f;
        if (s_keep[tid]) {
            int pos = 0;
            const int mi = s_idx[tid];
            for (int f = 0; f < nc; f++)
                if (s_keep[f] && s_idx[f] < mi) pos++;
            if (pos < TOPK) {
                g_topv[row * TOPK + pos] = s_val[tid];
                g_topi[row * TOPK + pos] = mi;
            }
        }
    }
}

// ---------------- sparse decode ----------------
__global__ void __launch_bounds__(256) dec_kernel(
    const float* __restrict__ Wd, const float* __restrict__ bd,
    float* __restrict__ recon) {
    __shared__ float sv[TOPK];
    __shared__ int   si[TOPK];
    const int row = blockIdx.x;
    const int tid = threadIdx.x;
    if (tid < TOPK) { sv[tid] = g_topv[row * TOPK + tid]; si[tid] = g_topi[row * TOPK + tid]; }
    __syncthreads();

    const int c0 = tid * 4;
    const int c1 = 1024 + tid * 4;
    float4 a0 = *(const float4*)(bd + c0);
    float4 a1 = *(const float4*)(bd + c1);
    #pragma unroll 4
    for (int j = 0; j < TOPK; j++) {
        const float v = sv[j];
        const float* wr = Wd + (size_t)si[j] * 2048;
        float4 w0 = *(const float4*)(wr + c0);
        float4 w1 = *(const float4*)(wr + c1);
        a0.x += v * w0.x; a0.y += v * w0.y; a0.z += v * w0.z; a0.w += v * w0.w;
        a1.x += v * w1.x; a1.y += v * w1.y; a1.z += v * w1.z; a1.w += v * w1.w;
    }
    float* out = recon + (size_t)row * 2048;
    *(float4*)(out + c0) = a0;
    *(float4*)(out + c1) = a1;
}

// ---------------- launch ----------------
extern "C" void kernel_launch(void* const* d_in, const int* in_sizes, int n_in,
                              void* d_out, int out_size) {
    const float* x     = (const float*)d_in[0];
    const float* W_enc = (const float*)d_in[1];
    const float* b_enc = (const float*)d_in[2];
    const float* W_dec = (const float*)d_in[3];
    const float* b_dec = (const float*)d_in[4];

    float* recon = (float*)d_out;
    float* zsp   = (float*)d_out + (size_t)M_ * 2048;

    cudaFuncSetAttribute(topk_kernel, cudaFuncAttributeMaxDynamicSharedMemorySize, 66560);
    cudaFuncSetAttribute(enc_gemm_mma, cudaFuncAttributeMaxDynamicSharedMemorySize, GEMM_SMEM);

    conv_x_kernel<<<(M_ * K_ + 255) / 256, 256>>>(x);
    conv_w_kernel<<<dim3(N_ / 32, K_ / 32), dim3(32, 8)>>>(W_enc);
    enc_gemm_mma<<<dim3(M_ / 128, N_ / 128), 256, GEMM_SMEM>>>(b_enc, zsp);
    topk_kernel<<<M_, 256, N_ * (int)sizeof(float)>>>(zsp);
    fixup_kernel<<<M_, 256>>>(x, b_enc, zsp);
    dec_kernel<<<M_, 256>>>(W_dec, b_dec, recon);
}

// round 10
// speedup vs baseline: 5.4827x; 1.2197x over previous
#include <cuda_runtime.h>
#include <cuda_bf16.h>
#include <stdint.h>

constexpr int M_ = 4096;     // batch B
constexpr int K_ = 2048;     // D
constexpr int N_ = 16384;    // L
constexpr int TOPK = 64;
constexpr float MARGIN = 0.06f;   // > 2*(9*sigma_gemm + bf16 half-ulp) = 2*0.022
constexpr int CANDCAP = 192;

// ---------------- scratch (device globals; no allocs allowed) ----------------
__device__ __align__(256) __nv_bfloat16 g_xhi[M_ * K_];
__device__ __align__(256) __nv_bfloat16 g_whiT[(size_t)N_ * K_];  // W_enc^T bf16 [N,K]
__device__ __align__(256) float g_wT[(size_t)N_ * K_];            // W_enc^T fp32 [N,K]
__device__ __align__(256) __nv_bfloat16 g_zbf[(size_t)M_ * N_];   // approx z, bf16
__device__ float g_topv[M_ * TOPK];
__device__ int   g_topi[M_ * TOPK];
__device__ int   g_cand[M_ * CANDCAP];   // idx | (above << 31)
__device__ int   g_ncand[M_];
__device__ int   g_nabove[M_];

// ---------------- helpers (family-safe ISA: sm_80/90 base) ----------------
__device__ __forceinline__ uint32_t smem_u32(const void* p) {
    uint32_t a;
    asm("{ .reg .u64 t; cvta.to.shared.u64 t, %1; cvt.u32.u64 %0, t; }" : "=r"(a) : "l"(p));
    return a;
}
__device__ __forceinline__ void cp_async16(uint32_t s, const void* g) {
    asm volatile("cp.async.cg.shared.global [%0], [%1], 16;" :: "r"(s), "l"(g));
}
__device__ __forceinline__ void ldmatrix4(uint32_t* r, uint32_t addr) {
    asm volatile("ldmatrix.sync.aligned.m8n8.x4.shared.b16 {%0,%1,%2,%3}, [%4];"
                 : "=r"(r[0]), "=r"(r[1]), "=r"(r[2]), "=r"(r[3]) : "r"(addr));
}
__device__ __forceinline__ void mma16816(float* d, const uint32_t* a, uint32_t b0, uint32_t b1) {
    asm volatile(
        "mma.sync.aligned.m16n8k16.row.col.f32.bf16.bf16.f32 "
        "{%0,%1,%2,%3}, {%4,%5,%6,%7}, {%8,%9}, {%0,%1,%2,%3};"
        : "+f"(d[0]), "+f"(d[1]), "+f"(d[2]), "+f"(d[3])
        : "r"(a[0]), "r"(a[1]), "r"(a[2]), "r"(a[3]), "r"(b0), "r"(b1));
}

// ---------------- conversion kernels ----------------
__global__ void __launch_bounds__(256) conv_x_kernel(const float* __restrict__ x) {
    int i = blockIdx.x * 256 + threadIdx.x;
    if (i < M_ * K_) g_xhi[i] = __float2bfloat16(x[i]);
}

// W_enc [K,N] -> transposed [N,K]: bf16 + fp32 copies
__global__ void __launch_bounds__(256) conv_w_kernel(const float* __restrict__ W) {
    __shared__ float t[32][33];
    const int tx = threadIdx.x, ty = threadIdx.y;   // 32 x 8
    const int n0 = blockIdx.x * 32, k0 = blockIdx.y * 32;
    #pragma unroll
    for (int j = 0; j < 4; j++)
        t[ty + j * 8][tx] = W[(size_t)(k0 + ty + j * 8) * N_ + (n0 + tx)];
    __syncthreads();
    #pragma unroll
    for (int j = 0; j < 4; j++) {
        float v = t[tx][ty + j * 8];
        size_t o = (size_t)(n0 + ty + j * 8) * K_ + (k0 + tx);
        g_whiT[o] = __float2bfloat16(v);
        g_wT[o] = v;
    }
}

// ---------------- bf16 encode GEMM via mma.sync (HMMA) -> g_zbf (device symbol) ----------------
constexpr int ROWB = 144;               // 64 bf16 = 128B, +16B pad (conflict-free ldmatrix)
constexpr int TILEB = 128 * ROWB;
constexpr int STAGEB = 2 * TILEB;
constexpr int GEMM_SMEM = 2 * STAGEB;   // 73728 B

__global__ void __launch_bounds__(256, 2) enc_gemm_mma(const float* __restrict__ b_enc) {
    extern __shared__ char sm[];
    const uint32_t base = smem_u32(sm);
    const int tid = threadIdx.x, lane = tid & 31, wid = tid >> 5;
    const int wm = wid & 3, wn = wid >> 2;          // 4x2 warp grid
    const int row0 = blockIdx.x * 128;              // M tile
    const int col0 = blockIdx.y * 128;              // N tile

    float c[2][8][4];
    #pragma unroll
    for (int i = 0; i < 2; i++)
        #pragma unroll
        for (int j = 0; j < 8; j++)
            #pragma unroll
            for (int q = 0; q < 4; q++) c[i][j][q] = 0.f;

    auto issue = [&](int ch) {
        const int kk = ch * 64;
        const uint32_t st = base + (ch & 1) * STAGEB;
        #pragma unroll
        for (int j = 0; j < 4; j++) {
            const int slot = tid + 256 * j;         // 0..1023
            const int r = slot >> 3, cc = slot & 7; // 128 rows x 8 x 16B
            cp_async16(st + r * ROWB + cc * 16,
                       g_xhi + (size_t)(row0 + r) * K_ + kk + cc * 8);
            cp_async16(st + TILEB + r * ROWB + cc * 16,
                       g_whiT + (size_t)(col0 + r) * K_ + kk + cc * 8);
        }
        asm volatile("cp.async.commit_group;");
    };

    auto compute = [&](int s) {
        const uint32_t sa = base + s * STAGEB;
        const uint32_t sb = sa + TILEB;
        #pragma unroll
        for (int ks = 0; ks < 4; ks++) {
            uint32_t a[2][4];
            #pragma unroll
            for (int mi = 0; mi < 2; mi++) {
                const int row = wm * 32 + mi * 16 + (lane & 15);
                ldmatrix4(a[mi], sa + row * ROWB + ks * 32 + ((lane >> 4) << 4));
            }
            uint32_t b[4][4];
            #pragma unroll
            for (int nl = 0; nl < 4; nl++) {
                const int row = wn * 64 + nl * 16 + (lane & 7) + ((lane >> 4) << 3);
                ldmatrix4(b[nl], sb + row * ROWB + ks * 32 + (((lane >> 3) & 1) << 4));
            }
            #pragma unroll
            for (int mi = 0; mi < 2; mi++)
                #pragma unroll
                for (int nl = 0; nl < 4; nl++) {
                    mma16816(c[mi][2 * nl + 0], a[mi], b[nl][0], b[nl][1]);
                    mma16816(c[mi][2 * nl + 1], a[mi], b[nl][2], b[nl][3]);
                }
        }
    };

    constexpr int NCH = 32;      // K=2048 / 64
    issue(0);
    for (int i = 0; i < NCH; i++) {
        if (i + 1 < NCH) {
            issue(i + 1);
            asm volatile("cp.async.wait_group 1;");
        } else {
            asm volatile("cp.async.wait_group 0;");
        }
        __syncthreads();
        compute(i & 1);
        __syncthreads();
    }

    const int gid = lane >> 2, tig = lane & 3;
    #pragma unroll
    for (int mi = 0; mi < 2; mi++) {
        const int r0 = row0 + wm * 32 + mi * 16 + gid;
        #pragma unroll
        for (int ni = 0; ni < 8; ni++) {
            const int cc = col0 + wn * 64 + ni * 8 + 2 * tig;
            const float2 bb = *(const float2*)(b_enc + cc);
            __nv_bfloat162 h0 = __float22bfloat162_rn(
                make_float2(c[mi][ni][0] + bb.x, c[mi][ni][1] + bb.y));
            __nv_bfloat162 h1 = __float22bfloat162_rn(
                make_float2(c[mi][ni][2] + bb.x, c[mi][ni][3] + bb.y));
            *(__nv_bfloat162*)(g_zbf + (size_t)r0 * N_ + cc) = h0;
            *(__nv_bfloat162*)(g_zbf + (size_t)(r0 + 8) * N_ + cc) = h1;
        }
    }
}

// ---------------- top-k on bf16 keys: 2-pass radix + candidate emit ----------------
__global__ void __launch_bounds__(256) topk_bf_kernel() {
    __shared__ uint32_t skey[N_ / 2];        // 8192 words, 2 keys each (32KB)
    __shared__ int hist[8][256];             // per-warp histograms (8KB)
    __shared__ int s_h1[256];
    __shared__ int s_b, s_r, s_T;
    __shared__ int s_nc, s_na;

    const int row = blockIdx.x;
    const int tid = threadIdx.x, wid = tid >> 5;

    for (int b = tid; b < 8 * 256; b += 256) ((int*)hist)[b] = 0;
    if (tid == 0) { s_nc = 0; s_na = 0; }
    __syncthreads();

    // pass 0: load row (2048 uint4), pack 15-bit keys, hist on top 8 bits (exponent)
    const uint4* zr = (const uint4*)(g_zbf + (size_t)row * N_);
    #pragma unroll
    for (int it = 0; it < 8; it++) {
        const int i4 = tid + it * 256;        // uint4 index: 8 bf16 each
        uint4 v = zr[i4];
        uint32_t wv[4] = { v.x, v.y, v.z, v.w };
        #pragma unroll
        for (int q = 0; q < 4; q++) {
            uint32_t lo = wv[q] & 0x7FFFu;
            uint32_t hi = (wv[q] >> 16) & 0x7FFFu;
            skey[i4 * 4 + q] = lo | (hi << 16);   // word w holds elements 2w, 2w+1
            atomicAdd(&hist[wid][lo >> 7], 1);
            atomicAdd(&hist[wid][hi >> 7], 1);
        }
    }
    __syncthreads();
    {
        int tot = 0;
        #pragma unroll
        for (int w = 0; w < 8; w++) tot += hist[w][tid];
        s_h1[tid] = tot;
    }
    __syncthreads();
    if (tid == 0) {
        int r = TOPK, b = 255;
        for (; b > 0; b--) { int cnt = s_h1[b]; if (cnt >= r) break; r -= cnt; }
        s_b = b; s_r = r;
    }
    __syncthreads();
    const int bsel = s_b;

    // pass 1: hist on low 7 bits within bucket bsel (all 8192 words)
    for (int b = tid; b < 8 * 256; b += 256) ((int*)hist)[b] = 0;
    __syncthreads();
    #pragma unroll
    for (int it = 0; it < 32; it++) {
        const int iw = tid + it * 256;        // 0..8191
        uint32_t pk = skey[iw];
        uint32_t lo = pk & 0xFFFFu, hi = pk >> 16;
        if ((int)(lo >> 7) == bsel) atomicAdd(&hist[wid][lo & 127u], 1);
        if ((int)(hi >> 7) == bsel) atomicAdd(&hist[wid][hi & 127u], 1);
    }
    __syncthreads();
    if (tid < 128) {
        int tot = 0;
        #pragma unroll
        for (int w = 0; w < 8; w++) tot += hist[w][tid];
        s_h1[tid] = tot;
    }
    __syncthreads();
    if (tid == 0) {
        int r = s_r, m = 127;
        for (; m > 0; m--) { int cnt = s_h1[m]; if (cnt >= r) break; r -= cnt; }
        s_T = (bsel << 7) | m;
    }
    __syncthreads();

    const float tval = __uint_as_float(((uint32_t)s_T) << 16);  // bf16 -> f32 exact
    const float blo = tval - MARGIN, bhi = tval + MARGIN;

    // pass 2: count above-band, emit candidates (|z| >= blo) over all 8192 words
    int myabove = 0;
    #pragma unroll
    for (int it = 0; it < 32; it++) {
        const int iw = tid + it * 256;        // 0..8191
        uint32_t pk = skey[iw];
        #pragma unroll
        for (int h = 0; h < 2; h++) {
            uint32_t key = h ? (pk >> 16) : (pk & 0xFFFFu);
            float av = __uint_as_float(key << 16);
            if (av >= blo) {
                bool above = (av > bhi);
                myabove += above ? 1 : 0;
                int p = atomicAdd(&s_nc, 1);
                if (p < CANDCAP)
                    g_cand[row * CANDCAP + p] = (iw * 2 + h) | (above ? 0x80000000 : 0);
            }
        }
    }
    atomicAdd(&s_na, myabove);
    __syncthreads();
    if (tid == 0) {
        g_ncand[row] = min(s_nc, CANDCAP);
        g_nabove[row] = s_na;
    }
}

// ---------------- exact fixup: fp32 dots, exact re-rank, scatter into zeroed z ----------------
__global__ void __launch_bounds__(256) fixup_kernel(
    const float* __restrict__ x, const float* __restrict__ b_enc,
    float* __restrict__ z) {
    __shared__ float sx[K_];
    __shared__ int   s_idx[CANDCAP];
    __shared__ float s_val[CANDCAP];
    __shared__ unsigned char s_abv[CANDCAP];
    __shared__ unsigned char s_keep[CANDCAP];

    const int row = blockIdx.x;
    const int tid = threadIdx.x, lid = tid & 31, wrp = tid >> 5;
    const int nc = g_ncand[row];
    const int slots = TOPK - g_nabove[row];

    for (int i = tid; i < K_; i += 256) sx[i] = x[(size_t)row * K_ + i];
    if (tid < nc) {
        int e = g_cand[row * CANDCAP + tid];
        s_idx[tid] = e & 0x7FFFFFFF;
        s_abv[tid] = (e >> 31) & 1;
        s_keep[tid] = 0;
    }
    __syncthreads();

    // exact fp32 dots against coalesced g_wT rows
    for (int c = wrp; c < nc; c += 8) {
        const int j = s_idx[c];
        const float* wr = g_wT + (size_t)j * K_;
        float a0 = 0.f, a1 = 0.f, a2 = 0.f, a3 = 0.f;
        for (int k = lid; k < K_; k += 128) {
            a0 = fmaf(sx[k],      wr[k],      a0);
            a1 = fmaf(sx[k + 32], wr[k + 32], a1);
            a2 = fmaf(sx[k + 64], wr[k + 64], a2);
            a3 = fmaf(sx[k + 96], wr[k + 96], a3);
        }
        float acc = (a0 + a1) + (a2 + a3);
        #pragma unroll
        for (int o = 16; o; o >>= 1) acc += __shfl_xor_sync(0xFFFFFFFFu, acc, o);
        if (lid == 0) s_val[c] = acc + b_enc[j];
    }
    __syncthreads();

    // keep: all above-band + top-`slots` band members by (|exact|, idx)
    if (tid < nc) {
        if (s_abv[tid]) {
            s_keep[tid] = 1;
        } else {
            const float mv = fabsf(s_val[tid]);
            const int mi = s_idx[tid];
            int rank = 0;
            for (int f = 0; f < nc; f++) {
                if (s_abv[f] || f == tid) continue;
                const float fv = fabsf(s_val[f]);
                if (fv > mv || (fv == mv && s_idx[f] < mi)) rank++;
            }
            s_keep[tid] = (rank < slots) ? 1 : 0;
        }
    }
    __syncthreads();

    // scatter exact kept values into zeroed z + final compact lists (index-ascending)
    float* zrow = z + (size_t)row * N_;
    if (tid < nc && s_keep[tid]) {
        const int mi = s_idx[tid];
        zrow[mi] = s_val[tid];
        int pos = 0;
        for (int f = 0; f < nc; f++)
            if (s_keep[f] && s_idx[f] < mi) pos++;
        if (pos < TOPK) {
            g_topv[row * TOPK + pos] = s_val[tid];
            g_topi[row * TOPK + pos] = mi;
        }
    }
}

// ---------------- sparse decode ----------------
__global__ void __launch_bounds__(256) dec_kernel(
    const float* __restrict__ Wd, const float* __restrict__ bd,
    float* __restrict__ recon) {
    __shared__ float sv[TOPK];
    __shared__ int   si[TOPK];
    const int row = blockIdx.x;
    const int tid = threadIdx.x;
    if (tid < TOPK) { sv[tid] = g_topv[row * TOPK + tid]; si[tid] = g_topi[row * TOPK + tid]; }
    __syncthreads();

    const int c0 = tid * 4;
    const int c1 = 1024 + tid * 4;
    float4 a0 = *(const float4*)(bd + c0);
    float4 a1 = *(const float4*)(bd + c1);
    #pragma unroll 2
    for (int j = 0; j < TOPK; j += 2) {
        const float va = sv[j], vb = sv[j + 1];
        const float* wra = Wd + (size_t)si[j] * 2048;
        const float* wrb = Wd + (size_t)si[j + 1] * 2048;
        float4 w0a = *(const float4*)(wra + c0);
        float4 w1a = *(const float4*)(wra + c1);
        float4 w0b = *(const float4*)(wrb + c0);
        float4 w1b = *(const float4*)(wrb + c1);
        a0.x += va * w0a.x; a0.y += va * w0a.y; a0.z += va * w0a.z; a0.w += va * w0a.w;
        a1.x += va * w1a.x; a1.y += va * w1a.y; a1.z += va * w1a.z; a1.w += va * w1a.w;
        a0.x += vb * w0b.x; a0.y += vb * w0b.y; a0.z += vb * w0b.z; a0.w += vb * w0b.w;
        a1.x += vb * w1b.x; a1.y += vb * w1b.y; a1.z += vb * w1b.z; a1.w += vb * w1b.w;
    }
    float* out = recon + (size_t)row * 2048;
    *(float4*)(out + c0) = a0;
    *(float4*)(out + c1) = a1;
}

// ---------------- launch ----------------
extern "C" void kernel_launch(void* const* d_in, const int* in_sizes, int n_in,
                              void* d_out, int out_size) {
    const float* x     = (const float*)d_in[0];
    const float* W_enc = (const float*)d_in[1];
    const float* b_enc = (const float*)d_in[2];
    const float* W_dec = (const float*)d_in[3];
    const float* b_dec = (const float*)d_in[4];

    float* recon = (float*)d_out;
    float* zsp   = (float*)d_out + (size_t)M_ * 2048;

    cudaFuncSetAttribute(enc_gemm_mma, cudaFuncAttributeMaxDynamicSharedMemorySize, GEMM_SMEM);

    cudaMemsetAsync(zsp, 0, (size_t)M_ * N_ * sizeof(float));
    conv_x_kernel<<<(M_ * K_ + 255) / 256, 256>>>(x);
    conv_w_kernel<<<dim3(N_ / 32, K_ / 32), dim3(32, 8)>>>(W_enc);
    enc_gemm_mma<<<dim3(M_ / 128, N_ / 128), 256, GEMM_SMEM>>>(b_enc);
    topk_bf_kernel<<<M_, 256>>>();
    fixup_kernel<<<M_, 256>>>(x, b_enc, zsp);
    dec_kernel<<<M_, 256>>>(W_dec, b_dec, recon);
}